// round 5
// baseline (speedup 1.0000x reference)
#include <cuda_runtime.h>

#define FULLMASK 0xFFFFFFFFu

#define HID   64
#define G4    256
#define RS    8
#define KIH   24
#define WIDTH 24
#define L0R   8
#define R0R   24
#define OW    16
#define GB    8          // batches per 4-warp group
#define NGRP  4
#define NTHR  512
#define CTAB  32

#define KQ_IN  6
#define KQ_HID 16
#define KQTOT  22

// smem float offsets
#define OFF_W    0
#define W_FLOATS (4*KQTOT*2*32*4)            // 22528 (4 gate-types, 22 quads, 2 k-pairs)
#define OFF_BIAS (OFF_W + W_FLOATS)          // 22528
#define OFF_WL   (OFF_BIAS + G4)             // 22784
#define OFF_BL   (OFF_WL + 3*HID)            // 22976
#define OFF_HX   (OFF_BL + 4)                // 22980 (16B-aligned: /4 ok)
#define HX_FLOATS (NGRP*GB*HID)              // 2048
#define OFF_XCH  (OFF_HX + HX_FLOATS)        // 25028
#define XCH_FLOATS (NGRP*4*GB*32*2)          // 8192
#define OFF_RBQ  (OFF_XCH + XCH_FLOATS)      // 33220
#define RBQ_FLOATS (NGRP*GB*3*WIDTH*4)       // 9216
#define SMEM_FLOATS (OFF_RBQ + RBQ_FLOATS)   // 42436 -> ~166 KB

typedef unsigned long long u64;

union F4U { float4 f4; struct { u64 lo, hi; } u; };

static __device__ __forceinline__ u64 pack2(float a, float b){
  u64 r; asm("mov.b64 %0, {%1, %2};" : "=l"(r) : "f"(a), "f"(b)); return r;
}
static __device__ __forceinline__ void unpack2(u64 v, float& a, float& b){
  asm("mov.b64 {%0, %1}, %2;" : "=f"(a), "=f"(b) : "l"(v));
}
static __device__ __forceinline__ u64 ffma2(u64 a, u64 b, u64 c){
  u64 d; asm("fma.rn.f32x2 %0, %1, %2, %3;" : "=l"(d) : "l"(a), "l"(b), "l"(c));
  return d;
}
static __device__ __forceinline__ float tanha(float x){
  float y; asm("tanh.approx.f32 %0, %1;" : "=f"(y) : "f"(x)); return y;
}
static __device__ __forceinline__ float sigf(float x){
  return fmaf(tanha(0.5f*x), 0.5f, 0.5f);
}

#define GBAR() asm volatile("bar.sync %0, 128;" :: "r"(grp + 1) : "memory")

__global__ void __launch_bounds__(NTHR, 1)
pixelrnn_kernel(const float* __restrict__ x,
                const float* __restrict__ W_ih,
                const float* __restrict__ W_hh,
                const float* __restrict__ b_ih,
                const float* __restrict__ b_hh,
                const float* __restrict__ Wl,
                const float* __restrict__ bl,
                float* __restrict__ out)
{
  extern __shared__ float sm[];
  const int tid  = threadIdx.x;
  const int warp = tid >> 5, lane = tid & 31;
  const int grp  = warp >> 2;          // 4-warp group, 8 batches
  const int q    = warp & 3;           // gate type: 0=i 1=f 2=g 3=o

  // ---- stage weights ----
  // float4 Wq[((qt*22 + kq)*2 + p)*32 + ln] =
  //   ( w(k,g0), w(k+1,g0), w(k,g1), w(k+1,g1) )
  //   g0 = 64*qt + ln, g1 = g0+32
  //   kq<6:  k = (kq>>1)*8 + (kq&1)*4 + 2p   (input,  W_ih col)
  //   kq>=6: k = 4*(kq-6) + 2p               (hidden, W_hh col)
  {
    float4* Wq = (float4*)(sm + OFF_W);
    for (int i = tid; i < 4*KQTOT*2*32; i += NTHR){
      int ln = i & 31;
      int p  = (i >> 5) & 1;
      int kq = (i >> 6) % KQTOT;
      int qt = (i >> 6) / KQTOT;
      int g0 = 64*qt + ln, g1 = g0 + 32;
      float4 v;
      if (kq < KQ_IN){
        int kk = (kq>>1)*8 + (kq&1)*4 + 2*p;
        v = make_float4(W_ih[g0*KIH + kk], W_ih[g0*KIH + kk + 1],
                        W_ih[g1*KIH + kk], W_ih[g1*KIH + kk + 1]);
      } else {
        int kk = 4*(kq - KQ_IN) + 2*p;
        v = make_float4(W_hh[g0*HID + kk], W_hh[g0*HID + kk + 1],
                        W_hh[g1*HID + kk], W_hh[g1*HID + kk + 1]);
      }
      Wq[i] = v;
    }
  }
  for (int i = tid; i < G4; i += NTHR) sm[OFF_BIAS + i] = b_ih[i] + b_hh[i];
  for (int i = tid; i < 3*HID; i += NTHR) sm[OFF_WL + i] = Wl[i];
  if (tid < 3) sm[OFF_BL + tid] = bl[tid];
  for (int i = tid; i < HX_FLOATS; i += NTHR) sm[OFF_HX + i] = 0.f;
  __syncthreads();

  const int bgrp = blockIdx.x * CTAB + grp * GB;
  float*  hxs = sm + OFF_HX + grp * (GB*HID);
  float2* xch = (float2*)(sm + OFF_XCH) + grp * (4*GB*32);
  float4* rbq = (float4*)(sm + OFF_RBQ) + grp * (GB*3*WIDTH);
  float*  rbf = (float*)rbq;
  const float4* wbase = (const float4*)(sm + OFF_W) + q*(KQTOT*2*32) + lane;

  const float bj0 = sm[OFF_BIAS + 64*q + lane];
  const float bj1 = sm[OFF_BIAS + 64*q + lane + 32];

  // warp owns batches 2q, 2q+1 for the cell update
  float cx0[2], cx1[2];
  cx0[0]=cx0[1]=cx1[0]=cx1[1]=0.f;

  float wl0[3], wl1[3], blv[3];
#pragma unroll
  for (int ch = 0; ch < 3; ch++){
    wl0[ch] = sm[OFF_WL + ch*HID + lane];
    wl1[ch] = sm[OFF_WL + ch*HID + lane + 32];
    blv[ch] = sm[OFF_BL + ch];
  }

  for (int r = L0R; r < R0R; r++){
    // row buffer init from x (4-replicated quads)
    for (int i = (warp & 3)*32 + lane; i < GB*3*WIDTH; i += 128){
      int b = i / (3*WIDTH);
      int rem = i - b*(3*WIDTH);
      int ch = rem / WIDTH;
      int base = rem - ch*WIDTH;
      const float* xr = x + (size_t)(bgrp + b)*(3*WIDTH*WIDTH)
                          + ch*(WIDTH*WIDTH) + r*WIDTH;
      float v0 = xr[base];
      float v1 = (base+1 < WIDTH) ? xr[base+1] : 0.f;
      float v2 = (base+2 < WIDTH) ? xr[base+2] : 0.f;
      float v3 = (base+3 < WIDTH) ? xr[base+3] : 0.f;
      rbq[i] = make_float4(v0, v1, v2, v3);
    }
    GBAR();

    for (int c = RS; c < WIDTH; c++){
      // acc[b][g]: u64 = (even-k partial, odd-k partial) for gate 64q+lane+32g
      u64 acc0[GB], acc1[GB];
#pragma unroll
      for (int b = 0; b < GB; b++){
        acc0[b] = pack2(bj0, 0.f);
        acc1[b] = pack2(bj1, 0.f);
      }

      // ---- input k-quads ----
#pragma unroll
      for (int kq = 0; kq < KQ_IN; kq++){
        F4U w0, w1;
        w0.f4 = wbase[(kq*2 + 0)*32];
        w1.f4 = wbase[(kq*2 + 1)*32];
        int ch = kq >> 1, qi = kq & 1;
        int base = c - RS + 4*qi;
#pragma unroll
        for (int b = 0; b < GB; b++){
          F4U a; a.f4 = rbq[(b*3 + ch)*WIDTH + base];
          acc0[b] = ffma2(a.u.lo, w0.u.lo, acc0[b]);
          acc1[b] = ffma2(a.u.lo, w0.u.hi, acc1[b]);
          acc0[b] = ffma2(a.u.hi, w1.u.lo, acc0[b]);
          acc1[b] = ffma2(a.u.hi, w1.u.hi, acc1[b]);
        }
      }

      // ---- hidden k-quads ----
#pragma unroll 4
      for (int kq = 0; kq < KQ_HID; kq++){
        F4U w0, w1;
        w0.f4 = wbase[((KQ_IN + kq)*2 + 0)*32];
        w1.f4 = wbase[((KQ_IN + kq)*2 + 1)*32];
#pragma unroll
        for (int b = 0; b < GB; b++){
          F4U a; a.f4 = *(const float4*)&hxs[b*HID + 4*kq];
          acc0[b] = ffma2(a.u.lo, w0.u.lo, acc0[b]);
          acc1[b] = ffma2(a.u.lo, w0.u.hi, acc1[b]);
          acc0[b] = ffma2(a.u.hi, w1.u.lo, acc0[b]);
          acc1[b] = ffma2(a.u.hi, w1.u.hi, acc1[b]);
        }
      }

      // ---- finalize + export: gate type q for all 8 batches ----
#pragma unroll
      for (int b = 0; b < GB; b++){
        float e0, o0, e1, o1;
        unpack2(acc0[b], e0, o0);
        unpack2(acc1[b], e1, o1);
        xch[(q*GB + b)*32 + lane] = make_float2(e0 + o0, e1 + o1);
      }
      GBAR();

      // ---- cell update for owned batches 2q, 2q+1 ----
      float p[2][3];
#pragma unroll
      for (int bb = 0; bb < 2; bb++){
        int b = 2*q + bb;
        float2 gi = xch[(0*GB + b)*32 + lane];
        float2 gf = xch[(1*GB + b)*32 + lane];
        float2 gg = xch[(2*GB + b)*32 + lane];
        float2 go = xch[(3*GB + b)*32 + lane];
        float c0 = sigf(gf.x)*cx0[bb] + sigf(gi.x)*tanha(gg.x);
        float c1 = sigf(gf.y)*cx1[bb] + sigf(gi.y)*tanha(gg.y);
        cx0[bb] = c0; cx1[bb] = c1;
        float h0 = sigf(go.x)*tanha(c0);
        float h1 = sigf(go.y)*tanha(c1);
        hxs[b*HID + lane]      = h0;
        hxs[b*HID + lane + 32] = h1;
#pragma unroll
        for (int ch = 0; ch < 3; ch++)
          p[bb][ch] = h0*wl0[ch] + h1*wl1[ch];
      }

      // butterfly-reduce the 6 head dot-products
#pragma unroll
      for (int off = 16; off >= 1; off >>= 1)
#pragma unroll
        for (int bb = 0; bb < 2; bb++)
#pragma unroll
          for (int ch = 0; ch < 3; ch++)
            p[bb][ch] += __shfl_xor_sync(FULLMASK, p[bb][ch], off);

      // leaky-relu, write v into replicated row-buffer quads + output
#pragma unroll
      for (int bb = 0; bb < 2; bb++)
#pragma unroll
        for (int ch = 0; ch < 3; ch++){
          if (lane == bb*3 + ch){
            float v = p[bb][ch] + blv[ch];
            v = fmaxf(v, 0.01f*v);
            int b = 2*q + bb;
#pragma unroll
            for (int t = 0; t < 4; t++)
              rbf[((b*3 + ch)*WIDTH + (c - t))*4 + t] = v;
            out[((size_t)(bgrp + b)*3 + ch)*(OW*OW)
                + (r - L0R)*OW + (c - RS)] = v;
          }
        }
      GBAR();
    }
  }
}

extern "C" void kernel_launch(void* const* d_in, const int* in_sizes, int n_in,
                              void* d_out, int out_size)
{
  const float* x    = (const float*)d_in[0];
  const float* W_ih = (const float*)d_in[1];
  const float* W_hh = (const float*)d_in[2];
  const float* b_ih = (const float*)d_in[3];
  const float* b_hh = (const float*)d_in[4];
  const float* Wl   = (const float*)d_in[5];
  const float* bl   = (const float*)d_in[6];

  int B = in_sizes[0] / (3*WIDTH*WIDTH);
  int grid = B / CTAB;   // 4096/32 = 128 CTAs

  size_t smem = SMEM_FLOATS * sizeof(float);   // ~166 KB
  cudaFuncSetAttribute(pixelrnn_kernel,
                       cudaFuncAttributeMaxDynamicSharedMemorySize, (int)smem);

  pixelrnn_kernel<<<grid, NTHR, smem>>>(x, W_ih, W_hh, b_ih, b_hh, Wl, bl,
                                        (float*)d_out);
}